// round 4
// baseline (speedup 1.0000x reference)
#include <cuda_runtime.h>
#include <cstdint>

#define T_SEQ 2048
#define NB    64
#define DIN   256
#define NH    256

// scratch: precomputed input projection xw[t][b][h]  (128 MB, static — no allocs)
__device__ float g_xw[(size_t)T_SEQ * NB * NH];

// padded h index: +4 floats of pad per 32-float window (bank de-conflict)
#define PHYS(k) ((k) + (((k) >> 5) << 2))
#define HPAD 288   // 256 + 8 windows * 4 pad

// ---------------- packed fp32x2 helpers (sm_100+) ----------------
__device__ __forceinline__ unsigned long long fma2(unsigned long long a,
                                                   unsigned long long b,
                                                   unsigned long long c) {
    unsigned long long d;
    asm("fma.rn.f32x2 %0, %1, %2, %3;" : "=l"(d) : "l"(a), "l"(b), "l"(c));
    return d;
}
__device__ __forceinline__ float f2sum(unsigned long long v) {
    float lo, hi;
    asm("mov.b64 {%0, %1}, %2;" : "=f"(lo), "=f"(hi) : "l"(v));
    return lo + hi;
}
__device__ __forceinline__ unsigned long long packf2(float lo, float hi) {
    unsigned long long r;
    asm("mov.b64 %0, {%1, %2};" : "=l"(r) : "f"(lo), "f"(hi));
    return r;
}
__device__ __forceinline__ uint32_t smem_u32(const void* p) {
    uint32_t a;
    asm("{ .reg .u64 t; cvta.to.shared.u64 t, %1; cvt.u32.u64 %0, t; }"
        : "=r"(a) : "l"(p));
    return a;
}
__device__ __forceinline__ uint32_t mapa_(uint32_t addr, int rank) {
    uint32_t r;
    asm("mapa.shared::cluster.u32 %0, %1, %2;" : "=r"(r) : "r"(addr), "r"(rank));
    return r;
}
__device__ __forceinline__ void cluster_sync_() {
    asm volatile("barrier.cluster.arrive.aligned;\n\t"
                 "barrier.cluster.wait.aligned;" ::: "memory");
}
__device__ __forceinline__ void st_cluster_b64(uint32_t addr, unsigned long long v) {
    asm volatile("st.shared::cluster.b64 [%0], %1;" :: "r"(addr), "l"(v) : "memory");
}
__device__ __forceinline__ void red_release_cta(uint32_t addr) {
    asm volatile("red.release.cta.shared::cta.add.u32 [%0], 1;"
                 :: "r"(addr) : "memory");
}
__device__ __forceinline__ void red_release_cluster(uint32_t addr) {
    asm volatile("red.release.cluster.shared::cluster.add.u32 [%0], 1;"
                 :: "r"(addr) : "memory");
}
__device__ __forceinline__ uint32_t ld_acq(uint32_t addr) {
    uint32_t v;
    asm volatile("ld.acquire.cluster.shared::cta.u32 %0, [%1];"
                 : "=r"(v) : "r"(addr) : "memory");
    return v;
}
__device__ __forceinline__ float tanh_fast(float x) {
    float e = __expf(2.0f * x);
    return 1.0f - __fdividef(2.0f, e + 1.0f);
}

// =================================================================
// Kernel 1: input projection  (unchanged — proven, ~issue-bound)
// =================================================================
__global__ void __launch_bounds__(256, 1)
xw_kernel(const float* __restrict__ x,
          const float* __restrict__ w_ih,
          const float* __restrict__ b_ih,
          const float* __restrict__ b_hh) {
    __shared__ __align__(16) float xs[8][256];
    __shared__ float pbuf[8 * 512];

    const int tid  = threadIdx.x;
    const int w    = tid >> 5;
    const int lane = tid & 31;
    const int kg   = w >> 1;
    const int og   = ((w & 1) << 5) | lane;
    const int half = blockIdx.y;
    const int rowbase0 = blockIdx.x * 128;

    unsigned long long wa[32], wb[32];
    {
        const int j0 = half * 128 + og, j1 = j0 + 64;
        const unsigned long long* p0 =
            (const unsigned long long*)(w_ih + (size_t)j0 * DIN + kg * 64);
        const unsigned long long* p1 =
            (const unsigned long long*)(w_ih + (size_t)j1 * DIN + kg * 64);
#pragma unroll
        for (int i = 0; i < 32; i++) { wa[i] = p0[i]; wb[i] = p1[i]; }
    }
    float bias = 0.f;
    if (tid < 128) bias = b_ih[half * 128 + tid] + b_hh[half * 128 + tid];

    const float4* xg = (const float4*)x;
    {
        int q = tid, r = q >> 6, c4 = q & 63;
        ((float4*)xs)[q]       = xg[(size_t)(rowbase0 + r) * 64 + c4];
        ((float4*)xs)[q + 256] = xg[(size_t)(rowbase0 + 4 + r) * 64 + c4];
    }
    __syncthreads();

    for (int it = 0; it < 16; it++) {
        const int rowbase = rowbase0 + it * 8;
        float4 n0, n1;
        if (it < 15) {
            int q = tid, r = q >> 6, c4 = q & 63;
            int nrb = rowbase + 8;
            n0 = xg[(size_t)(nrb + r) * 64 + c4];
            n1 = xg[(size_t)(nrb + 4 + r) * 64 + c4];
        }
        unsigned long long acc[8][2];
#pragma unroll
        for (int r = 0; r < 8; r++) { acc[r][0] = 0ull; acc[r][1] = 0ull; }
#pragma unroll
        for (int r = 0; r < 8; r++) {
            const ulonglong2* xp = (const ulonglong2*)&xs[r][kg * 64];
#pragma unroll
            for (int i = 0; i < 16; i++) {
                ulonglong2 hv = xp[i];
                acc[r][0] = fma2(wa[2 * i],     hv.x, acc[r][0]);
                acc[r][0] = fma2(wa[2 * i + 1], hv.y, acc[r][0]);
                acc[r][1] = fma2(wb[2 * i],     hv.x, acc[r][1]);
                acc[r][1] = fma2(wb[2 * i + 1], hv.y, acc[r][1]);
            }
        }
#pragma unroll
        for (int r = 0; r < 8; r++) {
            pbuf[r * 512 + kg * 128 + og]      = f2sum(acc[r][0]);
            pbuf[r * 512 + kg * 128 + og + 64] = f2sum(acc[r][1]);
        }
        __syncthreads();
        if (it < 15) {
            int q = tid;
            ((float4*)xs)[q]       = n0;
            ((float4*)xs)[q + 256] = n1;
        }
        if (tid < 128) {
#pragma unroll
            for (int r = 0; r < 8; r++) {
                float s = pbuf[r * 512 + tid] + pbuf[r * 512 + 128 + tid] +
                          pbuf[r * 512 + 256 + tid] + pbuf[r * 512 + 384 + tid] + bias;
                g_xw[(size_t)(rowbase + r) * NH + half * 128 + tid] = s;
            }
        }
        __syncthreads();
    }
}

// =================================================================
// Kernel 2: recurrence v4 — dataflow sync via monotonic counters.
//   64 clusters x 2 CTAs x 256 thr. CTA c owns cols [c*128,+128).
//   Warp w: cols c*128+16w..+16. Lane: cg=l&3 (4 cols), kp=l>>2 (32-k window,
//   rotated so kp<4 = local half). Writers = kp==0 (local window).
//   No barriers in the loop: producers push h via st.shared::cluster + a
//   release-red on per-(buffer,warp) monotonic counters; consumers
//   acquire-spin on the 2 counters covering their k-window.
// =================================================================
__global__ void __launch_bounds__(256, 1) __cluster_dims__(2, 1, 1)
rnn_kernel(const float* __restrict__ w_hh, float* __restrict__ out) {
    __shared__ __align__(16) float hbuf[2][HPAD];   // padded h, double-buffered
    // flags[buf][producerCTA][producerWarp] — monotonic counters (+4 per write)
    __shared__ __align__(16) uint32_t flags[2][2][8];

    const int tid  = threadIdx.x;
    const int w    = tid >> 5, l = tid & 31;
    const int cg   = l & 3,  kp = l >> 2;
    const int b    = blockIdx.x >> 1;
    const int c    = blockIdx.x & 1;
    const int peer = c ^ 1;
    const int j0   = c * 128 + w * 16 + cg * 4;       // 4 output cols
    const int k0   = (c * 128 + kp * 32) & 255;       // k-window (kp<4 local)
    const bool writer = (kp == 0);

    // register-resident weights: rows j0..j0+3, k in [k0, k0+32)
    unsigned long long wreg[4][16];
#pragma unroll
    for (int cc = 0; cc < 4; cc++) {
        const unsigned long long* wr =
            (const unsigned long long*)(w_hh + (size_t)(j0 + cc) * NH);
#pragma unroll
        for (int i = 0; i < 16; i++) wreg[cc][i] = wr[(k0 >> 1) + i];
    }

    // zero h buffers + flags
    for (int i = tid; i < 2 * HPAD; i += 256) ((float*)hbuf)[i] = 0.f;
    if (tid < 32) ((uint32_t*)flags)[tid] = 0u;

    // consumer flag addresses (2 producing warps per 32-k window), per buffer
    const int hf = k0 >> 7;                 // producing CTA of my window
    const int fw = (k0 & 127) >> 4;         // first producing warp (0,2,4,6)
    const uint32_t cf0[2] = { smem_u32(&flags[0][hf][fw]),
                              smem_u32(&flags[1][hf][fw]) };
    const uint32_t cf1[2] = { smem_u32(&flags[0][hf][fw + 1]),
                              smem_u32(&flags[1][hf][fw + 1]) };

    // writer addresses
    const int pj = PHYS(j0);
    const uint32_t lflag[2] = { smem_u32(&flags[0][c][w]),
                                smem_u32(&flags[1][c][w]) };
    const uint32_t rflag[2] = { mapa_(smem_u32(&flags[0][c][w]), peer),
                                mapa_(smem_u32(&flags[1][c][w]), peer) };
    const uint32_t rdst[2]  = { mapa_(smem_u32(&hbuf[0][pj]), peer),
                                mapa_(smem_u32(&hbuf[1][pj]), peer) };

    cluster_sync_();   // zeros + flag init visible cluster-wide

    float4 xc, x1, x2;
    if (writer) {
        xc = *(const float4*)&g_xw[(size_t)b * NH + j0];
        x1 = *(const float4*)&g_xw[((size_t)NB + b) * NH + j0];
    }

    for (int s = 0; s < T_SEQ; s++) {
        const int p = s & 1, q = p ^ 1;
        if (writer && s + 2 < T_SEQ)
            x2 = *(const float4*)&g_xw[((size_t)(s + 2) * NB + b) * NH + j0];

        // ---- wait for h(s): spin on the 2 counters covering my window ----
        if (s > 0) {
            const uint32_t tgt = 4u * (uint32_t)((s + 1) >> 1);
            uint32_t a = ld_acq(cf0[p]), bb = ld_acq(cf1[p]);
            while (a < tgt || bb < tgt) { a = ld_acq(cf0[p]); bb = ld_acq(cf1[p]); }
        }

        // ---- GEMV slice: 4 cols x 32 k (64 fma2, 8 LDS.128, bank-clean) ----
        const ulonglong2* hp = (const ulonglong2*)&hbuf[p][PHYS(k0)];
        unsigned long long a0 = 0ull, a1 = 0ull, a2 = 0ull, a3 = 0ull;
#pragma unroll
        for (int i = 0; i < 8; i++) {
            ulonglong2 hv = hp[i];
            a0 = fma2(wreg[0][2 * i], hv.x, a0);
            a0 = fma2(wreg[0][2 * i + 1], hv.y, a0);
            a1 = fma2(wreg[1][2 * i], hv.x, a1);
            a1 = fma2(wreg[1][2 * i + 1], hv.y, a1);
            a2 = fma2(wreg[2][2 * i], hv.x, a2);
            a2 = fma2(wreg[2][2 * i + 1], hv.y, a2);
            a3 = fma2(wreg[3][2 * i], hv.x, a3);
            a3 = fma2(wreg[3][2 * i + 1], hv.y, a3);
        }
        float v0 = f2sum(a0), v1 = f2sum(a1), v2 = f2sum(a2), v3 = f2sum(a3);
#pragma unroll
        for (int d = 4; d <= 16; d <<= 1) {   // butterfly over 8 k-parts
            v0 += __shfl_xor_sync(0xffffffffu, v0, d);
            v1 += __shfl_xor_sync(0xffffffffu, v1, d);
            v2 += __shfl_xor_sync(0xffffffffu, v2, d);
            v3 += __shfl_xor_sync(0xffffffffu, v3, d);
        }

        if (writer) {
            v0 = tanh_fast(v0 + xc.x);
            v1 = tanh_fast(v1 + xc.y);
            v2 = tanh_fast(v2 + xc.z);
            v3 = tanh_fast(v3 + xc.w);
            *(float4*)(out + ((size_t)s * NB + b) * NH + j0) =
                make_float4(v0, v1, v2, v3);
            if (s + 1 < T_SEQ) {
                *(float4*)&hbuf[q][pj] = make_float4(v0, v1, v2, v3);  // local
                st_cluster_b64(rdst[q],     packf2(v0, v1));           // remote
                st_cluster_b64(rdst[q] + 8, packf2(v2, v3));
                red_release_cta(lflag[q]);        // publish local
                red_release_cluster(rflag[q]);    // publish remote
            }
            xc = x1; x1 = x2;
        }
    }
    cluster_sync_();   // keep smem alive for in-flight peer stores
}

// =================================================================
extern "C" void kernel_launch(void* const* d_in, const int* in_sizes, int n_in,
                              void* d_out, int out_size) {
    const float* x    = (const float*)d_in[0];
    const float* w_ih = (const float*)d_in[1];
    const float* w_hh = (const float*)d_in[2];
    const float* b_ih = (const float*)d_in[3];
    const float* b_hh = (const float*)d_in[4];
    float* out = (float*)d_out;

    dim3 g1(1024, 2);
    xw_kernel<<<g1, 256>>>(x, w_ih, b_ih, b_hh);
    rnn_kernel<<<128, 256>>>(w_hh, out);
}

// round 5
// speedup vs baseline: 2.8403x; 2.8403x over previous
#include <cuda_runtime.h>
#include <cstdint>

#define T_SEQ 2048
#define NB    64
#define DIN   256
#define NH    256

// scratch: precomputed input projection xw[t][b][h]  (128 MB, static — no allocs)
__device__ float g_xw[(size_t)T_SEQ * NB * NH];

// padded h index: +4 floats of pad per 16-float window (bank de-conflict: the 8
// windows land on word offsets 20*kp -> distinct bank quads for every subload)
#define PHYS16(k) ((k) + (((k) >> 4) << 2))
#define HPAD2 320   // 256 + 16 windows * 4 pad

// ---------------- packed fp32x2 helpers (sm_100+) ----------------
__device__ __forceinline__ unsigned long long fma2(unsigned long long a,
                                                   unsigned long long b,
                                                   unsigned long long c) {
    unsigned long long d;
    asm("fma.rn.f32x2 %0, %1, %2, %3;" : "=l"(d) : "l"(a), "l"(b), "l"(c));
    return d;
}
__device__ __forceinline__ float f2sum(unsigned long long v) {
    float lo, hi;
    asm("mov.b64 {%0, %1}, %2;" : "=f"(lo), "=f"(hi) : "l"(v));
    return lo + hi;
}
__device__ __forceinline__ unsigned long long packf2(float lo, float hi) {
    unsigned long long r;
    asm("mov.b64 %0, {%1, %2};" : "=l"(r) : "f"(lo), "f"(hi));
    return r;
}
__device__ __forceinline__ uint32_t smem_u32(const void* p) {
    uint32_t a;
    asm("{ .reg .u64 t; cvta.to.shared.u64 t, %1; cvt.u32.u64 %0, t; }"
        : "=r"(a) : "l"(p));
    return a;
}
__device__ __forceinline__ uint32_t mapa_(uint32_t addr, int rank) {
    uint32_t r;
    asm("mapa.shared::cluster.u32 %0, %1, %2;" : "=r"(r) : "r"(addr), "r"(rank));
    return r;
}
__device__ __forceinline__ void cluster_sync_() {
    asm volatile("barrier.cluster.arrive.aligned;\n\t"
                 "barrier.cluster.wait.aligned;" ::: "memory");
}
__device__ __forceinline__ void cluster_arrive_() {
    asm volatile("barrier.cluster.arrive.aligned;" ::: "memory");
}
__device__ __forceinline__ void cluster_wait_() {
    asm volatile("barrier.cluster.wait.aligned;" ::: "memory");
}
__device__ __forceinline__ void st_cluster_b64(uint32_t addr, unsigned long long v) {
    asm volatile("st.shared::cluster.b64 [%0], %1;" :: "r"(addr), "l"(v) : "memory");
}
__device__ __forceinline__ float tanh_fast(float x) {
    float e = __expf(2.0f * x);
    return 1.0f - __fdividef(2.0f, e + 1.0f);
}

// =================================================================
// Kernel 1: input projection  (unchanged — proven)
// =================================================================
__global__ void __launch_bounds__(256, 1)
xw_kernel(const float* __restrict__ x,
          const float* __restrict__ w_ih,
          const float* __restrict__ b_ih,
          const float* __restrict__ b_hh) {
    __shared__ __align__(16) float xs[8][256];
    __shared__ float pbuf[8 * 512];

    const int tid  = threadIdx.x;
    const int w    = tid >> 5;
    const int lane = tid & 31;
    const int kg   = w >> 1;
    const int og   = ((w & 1) << 5) | lane;
    const int half = blockIdx.y;
    const int rowbase0 = blockIdx.x * 128;

    unsigned long long wa[32], wb[32];
    {
        const int j0 = half * 128 + og, j1 = j0 + 64;
        const unsigned long long* p0 =
            (const unsigned long long*)(w_ih + (size_t)j0 * DIN + kg * 64);
        const unsigned long long* p1 =
            (const unsigned long long*)(w_ih + (size_t)j1 * DIN + kg * 64);
#pragma unroll
        for (int i = 0; i < 32; i++) { wa[i] = p0[i]; wb[i] = p1[i]; }
    }
    float bias = 0.f;
    if (tid < 128) bias = b_ih[half * 128 + tid] + b_hh[half * 128 + tid];

    const float4* xg = (const float4*)x;
    {
        int q = tid, r = q >> 6, c4 = q & 63;
        ((float4*)xs)[q]       = xg[(size_t)(rowbase0 + r) * 64 + c4];
        ((float4*)xs)[q + 256] = xg[(size_t)(rowbase0 + 4 + r) * 64 + c4];
    }
    __syncthreads();

    for (int it = 0; it < 16; it++) {
        const int rowbase = rowbase0 + it * 8;
        float4 n0, n1;
        if (it < 15) {
            int q = tid, r = q >> 6, c4 = q & 63;
            int nrb = rowbase + 8;
            n0 = xg[(size_t)(nrb + r) * 64 + c4];
            n1 = xg[(size_t)(nrb + 4 + r) * 64 + c4];
        }
        unsigned long long acc[8][2];
#pragma unroll
        for (int r = 0; r < 8; r++) { acc[r][0] = 0ull; acc[r][1] = 0ull; }
#pragma unroll
        for (int r = 0; r < 8; r++) {
            const ulonglong2* xp = (const ulonglong2*)&xs[r][kg * 64];
#pragma unroll
            for (int i = 0; i < 16; i++) {
                ulonglong2 hv = xp[i];
                acc[r][0] = fma2(wa[2 * i],     hv.x, acc[r][0]);
                acc[r][0] = fma2(wa[2 * i + 1], hv.y, acc[r][0]);
                acc[r][1] = fma2(wb[2 * i],     hv.x, acc[r][1]);
                acc[r][1] = fma2(wb[2 * i + 1], hv.y, acc[r][1]);
            }
        }
#pragma unroll
        for (int r = 0; r < 8; r++) {
            pbuf[r * 512 + kg * 128 + og]      = f2sum(acc[r][0]);
            pbuf[r * 512 + kg * 128 + og + 64] = f2sum(acc[r][1]);
        }
        __syncthreads();
        if (it < 15) {
            int q = tid;
            ((float4*)xs)[q]       = n0;
            ((float4*)xs)[q + 256] = n1;
        }
        if (tid < 128) {
#pragma unroll
            for (int r = 0; r < 8; r++) {
                float s = pbuf[r * 512 + tid] + pbuf[r * 512 + 128 + tid] +
                          pbuf[r * 512 + 256 + tid] + pbuf[r * 512 + 384 + tid] + bias;
                g_xw[(size_t)(rowbase + r) * NH + half * 128 + tid] = s;
            }
        }
        __syncthreads();
    }
}

// =================================================================
// Kernel 2: recurrence v5 — split cluster barrier + local/remote k-split.
//   64 clusters x 2 CTAs x 256 thr. CTA c owns cols [c*128,+128).
//   Lane (w,l): cg=l&3 -> 4 cols j0..j0+3; kp=l>>2 -> 16 local k + 16 remote k.
//   Per step: [local FMA] -> cluster.wait -> [remote FMA] -> shfl reduce
//   -> tanh -> STS local + st.shared::cluster push -> cluster.arrive
//   -> STG out -> __syncthreads.
//   Exchange memory model identical to proven R1 (weak cluster stores ordered
//   by the aligned barrier's release/acquire). No smem reduce, no libm tanh.
// =================================================================
__global__ void __launch_bounds__(256, 1) __cluster_dims__(2, 1, 1)
rnn_kernel(const float* __restrict__ w_hh, float* __restrict__ out) {
    __shared__ __align__(16) float hbuf[2][HPAD2];   // padded, double-buffered

    const int tid  = threadIdx.x;
    const int w    = tid >> 5, l = tid & 31;
    const int cg   = l & 3,  kp = l >> 2;
    const int b    = blockIdx.x >> 1;
    const int c    = blockIdx.x & 1;
    const int peer = c ^ 1;
    const int j0   = c * 128 + w * 16 + cg * 4;   // 4 output cols
    const int lk   = c    * 128 + kp * 16;        // local  16-k window
    const int rk   = peer * 128 + kp * 16;        // remote 16-k window
    const bool writer = (kp == 0);

    // register-resident weights: 4 cols x (16 local + 16 remote) = 128 f32
    unsigned long long wl[4][8], wr[4][8];
#pragma unroll
    for (int cc = 0; cc < 4; cc++) {
        const float* row = w_hh + (size_t)(j0 + cc) * NH;
        const unsigned long long* pl = (const unsigned long long*)(row + lk);
        const unsigned long long* pr = (const unsigned long long*)(row + rk);
#pragma unroll
        for (int i = 0; i < 8; i++) { wl[cc][i] = pl[i]; wr[cc][i] = pr[i]; }
    }

    for (int i = tid; i < 2 * HPAD2; i += 256) ((float*)hbuf)[i] = 0.f;  // h0=0

    const int pj = PHYS16(j0);
    const uint32_t rdst[2] = { mapa_(smem_u32(&hbuf[0][pj]), peer),
                               mapa_(smem_u32(&hbuf[1][pj]), peer) };

    cluster_sync_();                              // zeros visible cluster-wide

    float4 xc, x1, x2;
    if (writer) {
        xc = *(const float4*)&g_xw[(size_t)b * NH + j0];
        x1 = *(const float4*)&g_xw[((size_t)NB + b) * NH + j0];
    }

    for (int s = 0; s < T_SEQ; s++) {
        const int p = s & 1, q = p ^ 1;
        if (writer && s + 2 < T_SEQ)
            x2 = *(const float4*)&g_xw[((size_t)(s + 2) * NB + b) * NH + j0];

        // ---- A: local-half FMA (own CTA's h, ready since last __syncthreads)
        unsigned long long a0 = 0ull, a1 = 0ull, a2 = 0ull, a3 = 0ull;
        {
            const ulonglong2* hp = (const ulonglong2*)&hbuf[p][PHYS16(lk)];
#pragma unroll
            for (int i = 0; i < 4; i++) {
                ulonglong2 hv = hp[i];
                a0 = fma2(wl[0][2 * i], hv.x, a0);
                a0 = fma2(wl[0][2 * i + 1], hv.y, a0);
                a1 = fma2(wl[1][2 * i], hv.x, a1);
                a1 = fma2(wl[1][2 * i + 1], hv.y, a1);
                a2 = fma2(wl[2][2 * i], hv.x, a2);
                a2 = fma2(wl[2][2 * i + 1], hv.y, a2);
                a3 = fma2(wl[3][2 * i], hv.x, a3);
                a3 = fma2(wl[3][2 * i + 1], hv.y, a3);
            }
        }

        // ---- B: wait for peer's h(s) pushes (matches arrive of step s-1)
        if (s) cluster_wait_();

        // ---- C: remote-half FMA
        {
            const ulonglong2* hp = (const ulonglong2*)&hbuf[p][PHYS16(rk)];
#pragma unroll
            for (int i = 0; i < 4; i++) {
                ulonglong2 hv = hp[i];
                a0 = fma2(wr[0][2 * i], hv.x, a0);
                a0 = fma2(wr[0][2 * i + 1], hv.y, a0);
                a1 = fma2(wr[1][2 * i], hv.x, a1);
                a1 = fma2(wr[1][2 * i + 1], hv.y, a1);
                a2 = fma2(wr[2][2 * i], hv.x, a2);
                a2 = fma2(wr[2][2 * i + 1], hv.y, a2);
                a3 = fma2(wr[3][2 * i], hv.x, a3);
                a3 = fma2(wr[3][2 * i + 1], hv.y, a3);
            }
        }
        float v0 = f2sum(a0), v1 = f2sum(a1), v2 = f2sum(a2), v3 = f2sum(a3);
#pragma unroll
        for (int d = 4; d <= 16; d <<= 1) {       // butterfly over 8 k-parts
            v0 += __shfl_xor_sync(0xffffffffu, v0, d);
            v1 += __shfl_xor_sync(0xffffffffu, v1, d);
            v2 += __shfl_xor_sync(0xffffffffu, v2, d);
            v3 += __shfl_xor_sync(0xffffffffu, v3, d);
        }

        if (writer) {
            v0 = tanh_fast(v0 + xc.x);
            v1 = tanh_fast(v1 + xc.y);
            v2 = tanh_fast(v2 + xc.z);
            v3 = tanh_fast(v3 + xc.w);
            if (s + 1 < T_SEQ) {
                *(float4*)&hbuf[q][pj] = make_float4(v0, v1, v2, v3);  // local
                st_cluster_b64(rdst[q],     packf2(v0, v1));           // remote
                st_cluster_b64(rdst[q] + 8, packf2(v2, v3));
            }
        }
        // ---- F: release my pushes; peers' wait(s+1) acquires them
        if (s + 1 < T_SEQ) cluster_arrive_();
        if (writer) {
            *(float4*)(out + ((size_t)s * NB + b) * NH + j0) =
                make_float4(v0, v1, v2, v3);
            xc = x1; x1 = x2;
        }
        __syncthreads();   // local-half stores visible CTA-wide for next A
    }
    cluster_sync_();       // keep smem alive for in-flight peer stores
}

// =================================================================
extern "C" void kernel_launch(void* const* d_in, const int* in_sizes, int n_in,
                              void* d_out, int out_size) {
    const float* x    = (const float*)d_in[0];
    const float* w_ih = (const float*)d_in[1];
    const float* w_hh = (const float*)d_in[2];
    const float* b_ih = (const float*)d_in[3];
    const float* b_hh = (const float*)d_in[4];
    float* out = (float*)d_out;

    dim3 g1(1024, 2);
    xw_kernel<<<g1, 256>>>(x, w_ih, b_ih, b_hh);
    rnn_kernel<<<128, 256>>>(w_hh, out);
}